// round 3
// baseline (speedup 1.0000x reference)
#include <cuda_runtime.h>
#include <math.h>
#include <stdint.h>

static constexpr int B_   = 4;
static constexpr int L_   = 1024;
static constexpr int D_   = 768;
static constexpr int H_   = 12;
static constexpr int HD_  = 64;
static constexpr int TQ_  = 64;
static constexpr int TK_  = 128;
static constexpr int NCH_ = L_ / TK_;          // 8
static constexpr int DYN_SMEM_FLOATS = 128*68 * 2;   // Es + Vs (>= Qs+Ks)
static constexpr int DYN_SMEM_BYTES  = DYN_SMEM_FLOATS * 4;  // 69632

// ---------------- device scratch (no allocations allowed) ----------------
__device__ float g_q[(size_t)B_ * L_ * D_];
__device__ float g_k[(size_t)B_ * L_ * D_];
__device__ float g_v[(size_t)B_ * L_ * D_];
__device__ float g_w[(size_t)B_ * L_ * D_];

// ---------------- SGEMM: C[M,N] = A[M,K] @ W[N,K]^T (+bias) --------------
// 128x128 block tile, Ktile=8, 256 threads, 8x8 micro-tile per thread.
__global__ __launch_bounds__(256)
void sgemm_nt_kernel(const float* __restrict__ A, const float* __restrict__ W,
                     const float* __restrict__ bias, float* __restrict__ C,
                     int M, int N, int K)
{
    __shared__ float As[8][132];
    __shared__ float Bs[8][132];
    const int m0 = blockIdx.y * 128;
    const int n0 = blockIdx.x * 128;
    const int tid = threadIdx.x;
    const int tx = tid & 15, ty = tid >> 4;
    const int lrow = tid >> 1;
    const int lk4  = (tid & 1) * 4;

    const float* Ap = A + (size_t)(m0 + lrow) * K + lk4;
    const float* Wp = W + (size_t)(n0 + lrow) * K + lk4;

    float acc[2][2][4][4];
    #pragma unroll
    for (int a = 0; a < 2; a++)
        #pragma unroll
        for (int b = 0; b < 2; b++)
            #pragma unroll
            for (int i = 0; i < 4; i++)
                #pragma unroll
                for (int j = 0; j < 4; j++) acc[a][b][i][j] = 0.f;

    for (int kt = 0; kt < K; kt += 8) {
        float4 av = *(const float4*)(Ap + kt);
        float4 wv = *(const float4*)(Wp + kt);
        As[lk4+0][lrow] = av.x; As[lk4+1][lrow] = av.y;
        As[lk4+2][lrow] = av.z; As[lk4+3][lrow] = av.w;
        Bs[lk4+0][lrow] = wv.x; Bs[lk4+1][lrow] = wv.y;
        Bs[lk4+2][lrow] = wv.z; Bs[lk4+3][lrow] = wv.w;
        __syncthreads();
        #pragma unroll
        for (int kk = 0; kk < 8; kk++) {
            float4 a0 = *(const float4*)&As[kk][ty*4];
            float4 a1 = *(const float4*)&As[kk][64 + ty*4];
            float4 b0 = *(const float4*)&Bs[kk][tx*4];
            float4 b1 = *(const float4*)&Bs[kk][64 + tx*4];
            float am[2][4] = {{a0.x,a0.y,a0.z,a0.w},{a1.x,a1.y,a1.z,a1.w}};
            float bn[2][4] = {{b0.x,b0.y,b0.z,b0.w},{b1.x,b1.y,b1.z,b1.w}};
            #pragma unroll
            for (int mi = 0; mi < 2; mi++)
                #pragma unroll
                for (int nj = 0; nj < 2; nj++)
                    #pragma unroll
                    for (int i = 0; i < 4; i++)
                        #pragma unroll
                        for (int j = 0; j < 4; j++)
                            acc[mi][nj][i][j] = fmaf(am[mi][i], bn[nj][j], acc[mi][nj][i][j]);
        }
        __syncthreads();
    }

    #pragma unroll
    for (int mi = 0; mi < 2; mi++) {
        #pragma unroll
        for (int i = 0; i < 4; i++) {
            int r = m0 + mi*64 + ty*4 + i;
            #pragma unroll
            for (int nj = 0; nj < 2; nj++) {
                int c = n0 + nj*64 + tx*4;
                float4 o;
                o.x = acc[mi][nj][i][0]; o.y = acc[mi][nj][i][1];
                o.z = acc[mi][nj][i][2]; o.w = acc[mi][nj][i][3];
                if (bias) {
                    o.x += bias[c+0]; o.y += bias[c+1];
                    o.z += bias[c+2]; o.w += bias[c+3];
                }
                *(float4*)&C[(size_t)r * N + c] = o;
            }
        }
    }
}

// ---------------- fused relative-position attention ----------------------
// One block per (b, h, 64-query-row tile). 256 threads (16x16).
// Pass 1: S = 8*(Q K^T + relbias) -> attn buffer (gmem, L2-hot), track rowmax.
// Pass 2: e = exp(S - max); rowsums + rel-v bucket sums + unnormalized PV;
//         write w = (w1 + w2)*invT to scratch.
// Pass 3: rewrite attn buffer with normalized probabilities.
__global__ __launch_bounds__(256)
void attn_kernel(const float* __restrict__ gq, const float* __restrict__ gk,
                 const float* __restrict__ gv,
                 const float* __restrict__ relk, const float* __restrict__ relv,
                 float* __restrict__ attn, float* __restrict__ gw)
{
    extern __shared__ float dsm[];
    float* Qs = dsm;              // [64][68]  (pass 1)   d-major: Qs[d][m]
    float* Ks = dsm + 64*68;      // [64][132] (pass 1)   d-major: Ks[d][n]
    float* Es = dsm;              // [128][68] (pass 2)   k-major: Es[k][m]
    float* Vs = dsm + 128*68;     // [128][68] (pass 2)   k-major: Vs[k][d]

    __shared__ float sh_relk[7*64];
    __shared__ float sh_relv[7*64];
    __shared__ float sh_bias[64*7];
    __shared__ float sh_rowmax[64];
    __shared__ float sh_T[64];
    __shared__ float sh_S0[64];
    __shared__ float sh_S6[64];
    __shared__ float sh_pmid[64*5];

    const int q0 = blockIdx.x * TQ_;
    const int h  = blockIdx.y;
    const int b  = blockIdx.z;
    const int tid = threadIdx.x;
    const int tx = tid & 15, ty = tid >> 4;

    for (int i = tid; i < 7*HD_; i += 256) { sh_relk[i] = relk[i]; sh_relv[i] = relv[i]; }
    for (int i = tid; i < 64*5; i += 256) sh_pmid[i] = 0.f;

    // ---- load Q tile transposed: Qs[d][m] ----
    const float* qbase = gq + ((size_t)(b*L_ + q0))*D_ + h*HD_;
    #pragma unroll
    for (int rep = 0; rep < 4; rep++) {
        int m  = rep*16 + (tid >> 4);
        int d0 = (tid & 15) * 4;
        float4 v = *(const float4*)(qbase + (size_t)m*D_ + d0);
        Qs[(d0+0)*68+m] = v.x; Qs[(d0+1)*68+m] = v.y;
        Qs[(d0+2)*68+m] = v.z; Qs[(d0+3)*68+m] = v.w;
    }
    __syncthreads();

    // ---- rel-k bias table: bias[m][r] = Q[m] . rel_k[r]  (unscaled) ----
    for (int idx = tid; idx < 64*7; idx += 256) {
        int m = idx / 7, r = idx % 7;
        float s = 0.f;
        #pragma unroll
        for (int d = 0; d < HD_; d++) s = fmaf(Qs[d*68+m], sh_relk[r*HD_+d], s);
        sh_bias[idx] = s;
    }
    __syncthreads();

    float pmax[4] = {-1e30f, -1e30f, -1e30f, -1e30f};
    float* attn_base = attn + (((size_t)(b*H_ + h))*L_ + q0) * L_;
    const float* kbase = gk + ((size_t)b*L_)*D_ + h*HD_;
    const float* vbase = gv + ((size_t)b*L_)*D_ + h*HD_;

    // ================= pass 1: logits =================
    for (int kc = 0; kc < NCH_; kc++) {
        const int k0 = kc * TK_;
        #pragma unroll
        for (int rep = 0; rep < 8; rep++) {
            int n  = rep*16 + (tid >> 4);
            int d0 = (tid & 15) * 4;
            float4 v = *(const float4*)(kbase + (size_t)(k0+n)*D_ + d0);
            Ks[(d0+0)*132+n] = v.x; Ks[(d0+1)*132+n] = v.y;
            Ks[(d0+2)*132+n] = v.z; Ks[(d0+3)*132+n] = v.w;
        }
        __syncthreads();

        float acc[4][8];
        #pragma unroll
        for (int i = 0; i < 4; i++)
            #pragma unroll
            for (int jj = 0; jj < 8; jj++) acc[i][jj] = 0.f;

        #pragma unroll 16
        for (int d = 0; d < HD_; d++) {
            float4 a  = *(const float4*)&Qs[d*68 + ty*4];
            float4 b0 = *(const float4*)&Ks[d*132 + tx*4];
            float4 b1 = *(const float4*)&Ks[d*132 + 64 + tx*4];
            float av[4] = {a.x, a.y, a.z, a.w};
            float bv[8] = {b0.x,b0.y,b0.z,b0.w, b1.x,b1.y,b1.z,b1.w};
            #pragma unroll
            for (int i = 0; i < 4; i++)
                #pragma unroll
                for (int jj = 0; jj < 8; jj++)
                    acc[i][jj] = fmaf(av[i], bv[jj], acc[i][jj]);
        }

        #pragma unroll
        for (int i = 0; i < 4; i++) {
            const int m  = ty*4 + i;
            const int qg = q0 + m;
            float out[8];
            #pragma unroll
            for (int jj = 0; jj < 8; jj++) {
                int col = (jj < 4) ? (tx*4 + jj) : (64 + tx*4 + (jj - 4));
                int kg  = k0 + col;
                int dlt = kg - qg;
                int r   = dlt < -3 ? 0 : (dlt > 3 ? 6 : dlt + 3);
                float s = 8.f * (acc[i][jj] + sh_bias[m*7 + r]);
                out[jj] = s;
                pmax[i] = fmaxf(pmax[i], s);
            }
            *(float4*)(attn_base + (size_t)m*L_ + k0 + tx*4)      = make_float4(out[0],out[1],out[2],out[3]);
            *(float4*)(attn_base + (size_t)m*L_ + k0 + 64 + tx*4) = make_float4(out[4],out[5],out[6],out[7]);
        }
        __syncthreads();
    }

    // row-max reduce across the 16 tx lanes of each ty group
    #pragma unroll
    for (int i = 0; i < 4; i++) {
        float v = pmax[i];
        #pragma unroll
        for (int off = 8; off > 0; off >>= 1)
            v = fmaxf(v, __shfl_xor_sync(0xffffffffu, v, off));
        if (tx == 0) sh_rowmax[ty*4 + i] = v;
    }
    __syncthreads();

    // ================= pass 2: exp + sums + PV =================
    float tsum[4]  = {0,0,0,0};
    float s0sum[4] = {0,0,0,0};
    float s6sum[4] = {0,0,0,0};
    float Wacc[4][4];
    #pragma unroll
    for (int i = 0; i < 4; i++)
        #pragma unroll
        for (int j = 0; j < 4; j++) Wacc[i][j] = 0.f;

    for (int kc = 0; kc < NCH_; kc++) {
        const int k0 = kc * TK_;
        #pragma unroll
        for (int rep = 0; rep < 8; rep++) {
            int n  = rep*16 + (tid >> 4);
            int d0 = (tid & 15) * 4;
            float4 v = *(const float4*)(vbase + (size_t)(k0+n)*D_ + d0);
            *(float4*)&Vs[n*68 + d0] = v;
        }
        #pragma unroll
        for (int i = 0; i < 4; i++) {
            const int m  = ty*4 + i;
            const int qg = q0 + m;
            const float rm = sh_rowmax[m];
            float4 s0v = *(const float4*)(attn_base + (size_t)m*L_ + k0 + tx*4);
            float4 s1v = *(const float4*)(attn_base + (size_t)m*L_ + k0 + 64 + tx*4);
            float sv[8] = {s0v.x,s0v.y,s0v.z,s0v.w, s1v.x,s1v.y,s1v.z,s1v.w};
            #pragma unroll
            for (int jj = 0; jj < 8; jj++) {
                int col = (jj < 4) ? (tx*4 + jj) : (64 + tx*4 + (jj - 4));
                int kg  = k0 + col;
                float e = __expf(sv[jj] - rm);
                tsum[i] += e;
                int dlt = kg - qg;
                if (dlt <= -3) s0sum[i] += e;
                if (dlt >=  3) s6sum[i] += e;
                if (dlt >= -2 && dlt <= 2) sh_pmid[m*5 + dlt + 2] = e;
                Es[col*68 + m] = e;
            }
        }
        __syncthreads();
        #pragma unroll 8
        for (int k = 0; k < TK_; k++) {
            float4 ev = *(const float4*)&Es[k*68 + ty*4];
            float4 vv = *(const float4*)&Vs[k*68 + tx*4];
            float em[4] = {ev.x, ev.y, ev.z, ev.w};
            float vn[4] = {vv.x, vv.y, vv.z, vv.w};
            #pragma unroll
            for (int i = 0; i < 4; i++)
                #pragma unroll
                for (int j = 0; j < 4; j++)
                    Wacc[i][j] = fmaf(em[i], vn[j], Wacc[i][j]);
        }
        __syncthreads();
    }

    // reduce row sums
    #pragma unroll
    for (int i = 0; i < 4; i++) {
        float t = tsum[i], s0 = s0sum[i], s6 = s6sum[i];
        #pragma unroll
        for (int off = 8; off > 0; off >>= 1) {
            t  += __shfl_xor_sync(0xffffffffu, t,  off);
            s0 += __shfl_xor_sync(0xffffffffu, s0, off);
            s6 += __shfl_xor_sync(0xffffffffu, s6, off);
        }
        if (tx == 0) { sh_T[ty*4+i] = t; sh_S0[ty*4+i] = s0; sh_S6[ty*4+i] = s6; }
    }
    __syncthreads();

    // w = (w1 + w2) * invT  -> scratch (head-interleaved [B,L,H,hd] = [4096,768])
    float* wbase = gw + ((size_t)(b*L_ + q0))*D_ + h*HD_;
    #pragma unroll
    for (int i = 0; i < 4; i++) {
        const int m = ty*4 + i;
        float T  = sh_T[m];
        float S0 = sh_S0[m];
        float S6 = sh_S6[m];
        float mids[5];
        #pragma unroll
        for (int r = 0; r < 5; r++) mids[r] = sh_pmid[m*5 + r];
        float inv = 1.f / T;
        float o[4];
        #pragma unroll
        for (int j = 0; j < 4; j++) {
            int d = tx*4 + j;
            float w2 = S0 * sh_relv[d] + S6 * sh_relv[6*64 + d];
            #pragma unroll
            for (int r = 0; r < 5; r++) w2 = fmaf(mids[r], sh_relv[(r+1)*64 + d], w2);
            o[j] = (Wacc[i][j] + w2) * inv;
        }
        *(float4*)(wbase + (size_t)m*D_ + tx*4) = make_float4(o[0], o[1], o[2], o[3]);
    }

    // ================= pass 3: normalized attn out =================
    for (int kc = 0; kc < NCH_; kc++) {
        const int k0 = kc * TK_;
        #pragma unroll
        for (int i = 0; i < 4; i++) {
            const int m = ty*4 + i;
            const float rm  = sh_rowmax[m];
            const float inv = 1.f / sh_T[m];
            float* p0 = attn_base + (size_t)m*L_ + k0 + tx*4;
            float* p1 = p0 + 64;
            float4 a0 = *(const float4*)p0;
            float4 a1 = *(const float4*)p1;
            a0.x = __expf(a0.x - rm) * inv; a0.y = __expf(a0.y - rm) * inv;
            a0.z = __expf(a0.z - rm) * inv; a0.w = __expf(a0.w - rm) * inv;
            a1.x = __expf(a1.x - rm) * inv; a1.y = __expf(a1.y - rm) * inv;
            a1.z = __expf(a1.z - rm) * inv; a1.w = __expf(a1.w - rm) * inv;
            *(float4*)p0 = a0;
            *(float4*)p1 = a1;
        }
    }
}

// ---------------- launch ----------------
extern "C" void kernel_launch(void* const* d_in, const int* in_sizes, int n_in,
                              void* d_out, int out_size)
{
    const float* query  = (const float*)d_in[0];
    const float* key    = (const float*)d_in[1];
    const float* value  = (const float*)d_in[2];
    const float* Wq     = (const float*)d_in[3];
    const float* Wk     = (const float*)d_in[4];
    const float* Wv     = (const float*)d_in[5];
    const float* Wproj  = (const float*)d_in[6];
    const float* b_proj = (const float*)d_in[7];
    const float* relk   = (const float*)d_in[8];
    const float* relv   = (const float*)d_in[9];

    float* out  = (float*)d_out;
    float* attn = out + (size_t)B_ * L_ * D_;   // x first, then attn

    float *gq, *gk, *gv, *gw;
    cudaGetSymbolAddress((void**)&gq, g_q);
    cudaGetSymbolAddress((void**)&gk, g_k);
    cudaGetSymbolAddress((void**)&gv, g_v);
    cudaGetSymbolAddress((void**)&gw, g_w);

    cudaFuncSetAttribute(attn_kernel, cudaFuncAttributeMaxDynamicSharedMemorySize,
                         DYN_SMEM_BYTES);

    dim3 gthr(256);
    dim3 ggrid(D_ / 128, (B_ * L_) / 128);   // 6 x 32

    sgemm_nt_kernel<<<ggrid, gthr>>>(query, Wq, nullptr, gq, B_*L_, D_, D_);
    sgemm_nt_kernel<<<ggrid, gthr>>>(key,   Wk, nullptr, gk, B_*L_, D_, D_);
    sgemm_nt_kernel<<<ggrid, gthr>>>(value, Wv, nullptr, gv, B_*L_, D_, D_);

    attn_kernel<<<dim3(L_/TQ_, H_, B_), 256, DYN_SMEM_BYTES>>>(
        gq, gk, gv, relk, relv, attn, gw);

    sgemm_nt_kernel<<<ggrid, gthr>>>(gw, Wproj, b_proj, out, B_*L_, D_, D_);
}

// round 4
// speedup vs baseline: 1.2101x; 1.2101x over previous
#include <cuda_runtime.h>
#include <math.h>
#include <stdint.h>

typedef unsigned long long u64;

static constexpr int B_  = 4;
static constexpr int L_  = 1024;
static constexpr int D_  = 768;
static constexpr int H_  = 12;
static constexpr int HD_ = 64;
static constexpr int TQ_ = 128;
static constexpr int TK_ = 128;
static constexpr int NCH_ = L_ / TK_;   // 8

// dynamic smem for attn: max(pass1: 2*64*132, pass2: 128*132 + 128*64) floats
static constexpr int DYN_SMEM_BYTES = (128*132 + 128*64) * 4;   // 100352

// ---------------- packed f32x2 helpers ----------------
__device__ __forceinline__ u64 pack2(float v) {
    u64 r; asm("mov.b64 %0, {%1, %1};" : "=l"(r) : "f"(v)); return r;
}
__device__ __forceinline__ void fma2(u64& c, u64 a, u64 b) {
    asm("fma.rn.f32x2 %0, %1, %2, %0;" : "+l"(c) : "l"(a), "l"(b));
}
__device__ __forceinline__ void add2(u64& c, u64 a) {
    asm("add.rn.f32x2 %0, %0, %1;" : "+l"(c) : "l"(a));
}
__device__ __forceinline__ float2 unp(u64 v) {
    float2 f; asm("mov.b64 {%0, %1}, %2;" : "=f"(f.x), "=f"(f.y) : "l"(v)); return f;
}

// ---------------- device scratch ----------------
__device__ float g_q[(size_t)B_ * L_ * D_];
__device__ float g_k[(size_t)B_ * L_ * D_];
__device__ float g_v[(size_t)B_ * L_ * D_];
__device__ float g_w[(size_t)B_ * L_ * D_];

// ---------------- SGEMM core: C[128,128] tile of A[M,768] @ W[768,768]^T ----
__device__ __forceinline__ void sgemm_128(const float* __restrict__ A,
                                          const float* __restrict__ W,
                                          const float* __restrict__ bias,
                                          float* __restrict__ C,
                                          int m0, int n0)
{
    __shared__ float As[8][132];
    __shared__ float Bs[8][132];
    const int tid  = threadIdx.x;
    const int tx   = tid & 15, ty = tid >> 4;
    const int lrow = tid >> 1;
    const int lk4  = (tid & 1) * 4;

    const float* Ap = A + (size_t)(m0 + lrow) * D_ + lk4;
    const float* Wp = W + (size_t)(n0 + lrow) * D_ + lk4;

    u64 acc[2][2][4][2] = {};

    for (int kt = 0; kt < D_; kt += 8) {
        float4 av = *(const float4*)(Ap + kt);
        float4 wv = *(const float4*)(Wp + kt);
        As[lk4+0][lrow] = av.x; As[lk4+1][lrow] = av.y;
        As[lk4+2][lrow] = av.z; As[lk4+3][lrow] = av.w;
        Bs[lk4+0][lrow] = wv.x; Bs[lk4+1][lrow] = wv.y;
        Bs[lk4+2][lrow] = wv.z; Bs[lk4+3][lrow] = wv.w;
        __syncthreads();
        #pragma unroll
        for (int kk = 0; kk < 8; kk++) {
            float4 a0 = *(const float4*)&As[kk][ty*4];
            float4 a1 = *(const float4*)&As[kk][64 + ty*4];
            ulonglong2 b0 = *(const ulonglong2*)&Bs[kk][tx*4];
            ulonglong2 b1 = *(const ulonglong2*)&Bs[kk][64 + tx*4];
            u64 ap[2][4] = {{pack2(a0.x), pack2(a0.y), pack2(a0.z), pack2(a0.w)},
                            {pack2(a1.x), pack2(a1.y), pack2(a1.z), pack2(a1.w)}};
            #pragma unroll
            for (int mi = 0; mi < 2; mi++)
                #pragma unroll
                for (int i = 0; i < 4; i++) {
                    fma2(acc[mi][0][i][0], ap[mi][i], b0.x);
                    fma2(acc[mi][0][i][1], ap[mi][i], b0.y);
                    fma2(acc[mi][1][i][0], ap[mi][i], b1.x);
                    fma2(acc[mi][1][i][1], ap[mi][i], b1.y);
                }
        }
        __syncthreads();
    }

    #pragma unroll
    for (int mi = 0; mi < 2; mi++)
        #pragma unroll
        for (int i = 0; i < 4; i++) {
            int r = m0 + mi*64 + ty*4 + i;
            #pragma unroll
            for (int nj = 0; nj < 2; nj++) {
                int c = n0 + nj*64 + tx*4;
                float2 p0 = unp(acc[mi][nj][i][0]);
                float2 p1 = unp(acc[mi][nj][i][1]);
                float4 o = make_float4(p0.x, p0.y, p1.x, p1.y);
                if (bias) {
                    o.x += bias[c+0]; o.y += bias[c+1];
                    o.z += bias[c+2]; o.w += bias[c+3];
                }
                *(float4*)&C[(size_t)r * D_ + c] = o;
            }
        }
}

__global__ __launch_bounds__(256)
void sgemm_qkv_kernel(const float* __restrict__ Aq, const float* __restrict__ Ak,
                      const float* __restrict__ Av,
                      const float* __restrict__ Wq, const float* __restrict__ Wk,
                      const float* __restrict__ Wv,
                      float* __restrict__ Cq, float* __restrict__ Ck,
                      float* __restrict__ Cv)
{
    const int sel = blockIdx.x / 6;
    const int n0  = (blockIdx.x % 6) * 128;
    const int m0  = blockIdx.y * 128;
    const float* A = (sel == 0) ? Aq : (sel == 1) ? Ak : Av;
    const float* W = (sel == 0) ? Wq : (sel == 1) ? Wk : Wv;
    float*       C = (sel == 0) ? Cq : (sel == 1) ? Ck : Cv;
    sgemm_128(A, W, nullptr, C, m0, n0);
}

__global__ __launch_bounds__(256)
void sgemm_proj_kernel(const float* __restrict__ A, const float* __restrict__ W,
                       const float* __restrict__ bias, float* __restrict__ C)
{
    sgemm_128(A, W, bias, C, blockIdx.y * 128, blockIdx.x * 128);
}

// ---------------- fused relative-position attention ----------------------
// One block per (b, h, 128-query-row tile). 256 threads.
__global__ __launch_bounds__(256, 2)
void attn_kernel(const float* __restrict__ gq, const float* __restrict__ gk,
                 const float* __restrict__ gv,
                 const float* __restrict__ relk, const float* __restrict__ relv,
                 float* __restrict__ attn, float* __restrict__ gw)
{
    extern __shared__ float dsm[];
    float* Qs = dsm;              // pass1: [64][132]  d-major
    float* Ks = dsm + 64*132;     // pass1: [64][132]  d-major
    float* Es = dsm;              // pass2: [128][132] k-major (transposed e)
    float* Vs = dsm + 128*132;    // pass2: [128][64]  row-major

    __shared__ float sh_relk[7*HD_];
    __shared__ float sh_relv[7*HD_];
    __shared__ float sh_bias[TQ_*7];
    __shared__ float sh_rowmax[TQ_];
    __shared__ float sh_T[TQ_];
    __shared__ float sh_S0[TQ_];
    __shared__ float sh_S6[TQ_];
    __shared__ float sh_pmid[TQ_*5];

    const int q0  = blockIdx.x * TQ_;
    const int h   = blockIdx.y;
    const int b   = blockIdx.z;
    const int tid = threadIdx.x;
    const int tx  = tid & 15, ty = tid >> 4;
    const int lrow = tid >> 1;          // 0..127
    const int lk4  = (tid & 1) * 4;

    for (int i = tid; i < 7*HD_; i += 256) { sh_relk[i] = relk[i]; sh_relv[i] = relv[i]; }
    for (int i = tid; i < TQ_*5; i += 256) sh_pmid[i] = 0.f;

    const float* qbase = gq + ((size_t)(b*L_ + q0))*D_ + h*HD_;
    const float* kbase = gk + ((size_t)b*L_)*D_ + h*HD_;
    const float* vbase = gv + ((size_t)b*L_)*D_ + h*HD_;
    float* attn_base = attn + (((size_t)(b*H_ + h))*L_ + q0) * L_;

    // ---- Q tile transposed: Qs[d][m], 2-way-conflict STS mapping ----
    #pragma unroll
    for (int r = 0; r < 8; r++) {
        int d = lk4 + r*8;
        float4 v = *(const float4*)(qbase + (size_t)lrow*D_ + d);
        Qs[(d+0)*132 + lrow] = v.x; Qs[(d+1)*132 + lrow] = v.y;
        Qs[(d+2)*132 + lrow] = v.z; Qs[(d+3)*132 + lrow] = v.w;
    }
    __syncthreads();

    // ---- rel-k bias: bias[m][r] = Q[m] . rel_k[r] ----
    for (int idx = tid; idx < TQ_*7; idx += 256) {
        int m = idx / 7, r = idx % 7;
        float s = 0.f;
        #pragma unroll
        for (int d = 0; d < HD_; d++) s = fmaf(Qs[d*132 + m], sh_relk[r*HD_ + d], s);
        sh_bias[idx] = s;
    }

    float pmax[2][4];
    #pragma unroll
    for (int mi = 0; mi < 2; mi++)
        #pragma unroll
        for (int i = 0; i < 4; i++) pmax[mi][i] = -1e30f;

    // ================= pass 1: logits =================
    for (int kc = 0; kc < NCH_; kc++) {
        const int k0 = kc * TK_;
        #pragma unroll
        for (int r = 0; r < 8; r++) {
            int d = lk4 + r*8;
            float4 v = *(const float4*)(kbase + (size_t)(k0 + lrow)*D_ + d);
            Ks[(d+0)*132 + lrow] = v.x; Ks[(d+1)*132 + lrow] = v.y;
            Ks[(d+2)*132 + lrow] = v.z; Ks[(d+3)*132 + lrow] = v.w;
        }
        __syncthreads();

        u64 acc[2][2][4][2] = {};
        #pragma unroll 8
        for (int d = 0; d < HD_; d++) {
            float4 a0 = *(const float4*)&Qs[d*132 + ty*4];
            float4 a1 = *(const float4*)&Qs[d*132 + 64 + ty*4];
            ulonglong2 b0 = *(const ulonglong2*)&Ks[d*132 + tx*4];
            ulonglong2 b1 = *(const ulonglong2*)&Ks[d*132 + 64 + tx*4];
            u64 ap[2][4] = {{pack2(a0.x), pack2(a0.y), pack2(a0.z), pack2(a0.w)},
                            {pack2(a1.x), pack2(a1.y), pack2(a1.z), pack2(a1.w)}};
            #pragma unroll
            for (int mi = 0; mi < 2; mi++)
                #pragma unroll
                for (int i = 0; i < 4; i++) {
                    fma2(acc[mi][0][i][0], ap[mi][i], b0.x);
                    fma2(acc[mi][0][i][1], ap[mi][i], b0.y);
                    fma2(acc[mi][1][i][0], ap[mi][i], b1.x);
                    fma2(acc[mi][1][i][1], ap[mi][i], b1.y);
                }
        }

        #pragma unroll
        for (int mi = 0; mi < 2; mi++)
            #pragma unroll
            for (int i = 0; i < 4; i++) {
                const int m  = mi*64 + ty*4 + i;
                const int qg = q0 + m;
                const float* brow = &sh_bias[m*7];
                #pragma unroll
                for (int nj = 0; nj < 2; nj++) {
                    float2 p0 = unp(acc[mi][nj][i][0]);
                    float2 p1 = unp(acc[mi][nj][i][1]);
                    float vv[4] = {p0.x, p0.y, p1.x, p1.y};
                    float o[4];
                    #pragma unroll
                    for (int j = 0; j < 4; j++) {
                        int kg  = k0 + nj*64 + tx*4 + j;
                        int dlt = kg - qg;
                        int rr  = dlt < -3 ? 0 : (dlt > 3 ? 6 : dlt + 3);
                        float s = 8.f * (vv[j] + brow[rr]);
                        o[j] = s;
                        pmax[mi][i] = fmaxf(pmax[mi][i], s);
                    }
                    *(float4*)(attn_base + (size_t)m*L_ + k0 + nj*64 + tx*4)
                        = make_float4(o[0], o[1], o[2], o[3]);
                }
            }
        __syncthreads();
    }

    // ---- row-max reduce over the 16 tx lanes ----
    #pragma unroll
    for (int mi = 0; mi < 2; mi++)
        #pragma unroll
        for (int i = 0; i < 4; i++) {
            float v = pmax[mi][i];
            #pragma unroll
            for (int off = 8; off > 0; off >>= 1)
                v = fmaxf(v, __shfl_xor_sync(0xffffffffu, v, off));
            if (tx == 0) sh_rowmax[mi*64 + ty*4 + i] = v;
        }
    __syncthreads();

    // ================= pass 2: exp + sums + PV (k-split-2) =================
    const int g    = tid >> 7;       // 0/1: k-split group
    const int t2   = tid & 127;
    const int txd  = t2 & 7;         // 8 d's per thread
    const int tym  = t2 >> 3;        // 16 m-groups

    const int m2   = lrow;           // exp-stage row
    const int c0   = lk4;
    const int qg2  = q0 + m2;
    const float rm2 = sh_rowmax[m2];

    float tsum = 0.f, s0sum = 0.f, s6sum = 0.f;
    u64 wacc[2][4][4] = {};

    for (int kc = 0; kc < NCH_; kc++) {
        const int k0 = kc * TK_;
        // V loader (row-major, coalesced, conflict-free)
        #pragma unroll
        for (int r = 0; r < 8; r++) {
            int n = r*16 + ty;
            float4 v = *(const float4*)(vbase + (size_t)(k0 + n)*D_ + tx*4);
            *(float4*)&Vs[n*64 + tx*4] = v;
        }
        // exp stage: row m2, cols c0 + 8r (+j); transposed STS with 2-way mapping
        #pragma unroll
        for (int r = 0; r < 16; r++) {
            int c = c0 + 8*r;
            float4 sv = *(const float4*)(attn_base + (size_t)m2*L_ + k0 + c);
            float svv[4] = {sv.x, sv.y, sv.z, sv.w};
            #pragma unroll
            for (int j = 0; j < 4; j++) {
                float e = __expf(svv[j] - rm2);
                tsum += e;
                int dlt = k0 + c + j - qg2;
                if (dlt <= -3)      s0sum += e;
                else if (dlt >= 3)  s6sum += e;
                else                sh_pmid[m2*5 + dlt + 2] = e;
                Es[(c+j)*132 + m2] = e;
            }
        }
        __syncthreads();
        // PV: each group handles 64 k's with 8x8 micro-tile
        #pragma unroll 4
        for (int kk = 0; kk < 64; kk++) {
            int k = g*64 + kk;
            float4 e0 = *(const float4*)&Es[k*132 + tym*4];
            float4 e1 = *(const float4*)&Es[k*132 + 64 + tym*4];
            ulonglong2 v0 = *(const ulonglong2*)&Vs[k*64 + txd*8];
            ulonglong2 v1 = *(const ulonglong2*)&Vs[k*64 + txd*8 + 4];
            u64 ep[2][4] = {{pack2(e0.x), pack2(e0.y), pack2(e0.z), pack2(e0.w)},
                            {pack2(e1.x), pack2(e1.y), pack2(e1.z), pack2(e1.w)}};
            #pragma unroll
            for (int mi = 0; mi < 2; mi++)
                #pragma unroll
                for (int i = 0; i < 4; i++) {
                    fma2(wacc[mi][i][0], ep[mi][i], v0.x);
                    fma2(wacc[mi][i][1], ep[mi][i], v0.y);
                    fma2(wacc[mi][i][2], ep[mi][i], v1.x);
                    fma2(wacc[mi][i][3], ep[mi][i], v1.y);
                }
        }
        __syncthreads();
    }

    // ---- row-sum pair reduce (two threads per row) ----
    tsum  += __shfl_xor_sync(0xffffffffu, tsum,  1);
    s0sum += __shfl_xor_sync(0xffffffffu, s0sum, 1);
    s6sum += __shfl_xor_sync(0xffffffffu, s6sum, 1);
    if ((tid & 1) == 0) { sh_T[m2] = tsum; sh_S0[m2] = s0sum; sh_S6[m2] = s6sum; }
    __syncthreads();

    // ---- k-split pair reduce via smem (reuse Es region) ----
    if (g == 1) {
        #pragma unroll
        for (int mi = 0; mi < 2; mi++)
            #pragma unroll
            for (int i = 0; i < 4; i++)
                #pragma unroll
                for (int p = 0; p < 4; p++)
                    *(u64*)&dsm[t2*64 + ((mi*4 + i)*4 + p)*2] = wacc[mi][i][p];
    }
    __syncthreads();
    if (g == 0) {
        #pragma unroll
        for (int mi = 0; mi < 2; mi++)
            #pragma unroll
            for (int i = 0; i < 4; i++)
                #pragma unroll
                for (int p = 0; p < 4; p++)
                    add2(wacc[mi][i][p], *(const u64*)&dsm[t2*64 + ((mi*4 + i)*4 + p)*2]);

        // ---- w = (w1 + w2) * invT -> scratch [B,L,H,hd] ----
        float* wbase = gw + ((size_t)(b*L_ + q0))*D_ + h*HD_;
        #pragma unroll
        for (int mi = 0; mi < 2; mi++)
            #pragma unroll
            for (int i = 0; i < 4; i++) {
                const int m = mi*64 + tym*4 + i;
                float T  = sh_T[m];
                float S0 = sh_S0[m];
                float S6 = sh_S6[m];
                float inv = 1.f / T;
                float mids[5];
                #pragma unroll
                for (int r = 0; r < 5; r++) mids[r] = sh_pmid[m*5 + r];
                float o[8];
                #pragma unroll
                for (int p = 0; p < 4; p++) {
                    float2 u = unp(wacc[mi][i][p]);
                    o[2*p] = u.x; o[2*p + 1] = u.y;
                }
                #pragma unroll
                for (int j = 0; j < 8; j++) {
                    int d = txd*8 + j;
                    float w2 = S0 * sh_relv[d] + S6 * sh_relv[6*HD_ + d];
                    #pragma unroll
                    for (int r = 0; r < 5; r++)
                        w2 = fmaf(mids[r], sh_relv[(r+1)*HD_ + d], w2);
                    o[j] = (o[j] + w2) * inv;
                }
                *(float4*)(wbase + (size_t)m*D_ + txd*8)     = make_float4(o[0], o[1], o[2], o[3]);
                *(float4*)(wbase + (size_t)m*D_ + txd*8 + 4) = make_float4(o[4], o[5], o[6], o[7]);
            }
    }

    // ================= pass 3: normalized attn out =================
    const float inv3 = 1.f / sh_T[m2];
    #pragma unroll 4
    for (int r = 0; r < 128; r++) {
        int c = c0 + 8*r;
        float* p = attn_base + (size_t)m2*L_ + c;
        float4 a = *(const float4*)p;
        a.x = __expf(a.x - rm2) * inv3;
        a.y = __expf(a.y - rm2) * inv3;
        a.z = __expf(a.z - rm2) * inv3;
        a.w = __expf(a.w - rm2) * inv3;
        *(float4*)p = a;
    }
}

// ---------------- launch ----------------
extern "C" void kernel_launch(void* const* d_in, const int* in_sizes, int n_in,
                              void* d_out, int out_size)
{
    const float* query  = (const float*)d_in[0];
    const float* key    = (const float*)d_in[1];
    const float* value  = (const float*)d_in[2];
    const float* Wq     = (const float*)d_in[3];
    const float* Wk     = (const float*)d_in[4];
    const float* Wv     = (const float*)d_in[5];
    const float* Wproj  = (const float*)d_in[6];
    const float* b_proj = (const float*)d_in[7];
    const float* relk   = (const float*)d_in[8];
    const float* relv   = (const float*)d_in[9];

    float* out  = (float*)d_out;
    float* attn = out + (size_t)B_ * L_ * D_;   // x first, then attn

    float *gq, *gk, *gv, *gw;
    cudaGetSymbolAddress((void**)&gq, g_q);
    cudaGetSymbolAddress((void**)&gk, g_k);
    cudaGetSymbolAddress((void**)&gv, g_v);
    cudaGetSymbolAddress((void**)&gw, g_w);

    cudaFuncSetAttribute(attn_kernel, cudaFuncAttributeMaxDynamicSharedMemorySize,
                         DYN_SMEM_BYTES);

    sgemm_qkv_kernel<<<dim3(18, 32), 256>>>(query, key, value, Wq, Wk, Wv, gq, gk, gv);

    attn_kernel<<<dim3(L_/TQ_, H_, B_), 256, DYN_SMEM_BYTES>>>(
        gq, gk, gv, relk, relv, attn, gw);

    sgemm_proj_kernel<<<dim3(6, 32), 256>>>(gw, Wproj, b_proj, out);
}